// round 2
// baseline (speedup 1.0000x reference)
#include <cuda_runtime.h>
#include <cuda_bf16.h>
#include <math.h>

// Problem constants:
//  x: [16, 512, 64, 64] fp32 == [64 batches][128 ch][4096 pix] contiguous
#define NB     64
#define CI     128
#define NPIX   4096
#define KSPLIT 8
#define KCHUNK (NPIX / KSPLIT)   // 512
#define PAD    132               // smem matrix stride (128 + 4)
#define SDUP   264               // duplicated-array stride (256 + 8)
#define SNORM  132

typedef unsigned long long ull;

// ---------------- packed fp32x2 helpers ----------------
__device__ __forceinline__ void ffma2(ull& d, ull a, ull b) {
    asm("fma.rn.f32x2 %0, %1, %2, %0;" : "+l"(d) : "l"(a), "l"(b));
}
__device__ __forceinline__ ull dup2(float x) {
    ull d;
    asm("mov.b64 %0, {%1, %1};" : "=l"(d) : "f"(x));
    return d;
}
__device__ __forceinline__ float2 unpk(ull v) {
    float2 r;
    asm("mov.b64 {%0, %1}, %2;" : "=f"(r.x), "=f"(r.y) : "l"(v));
    return r;
}
__device__ __forceinline__ float lo32(ull v) {
    return __uint_as_float((unsigned)(v & 0xffffffffULL));
}

// ---------------- scratch (no allocations allowed) ----------------
__device__ float g_Gpart[NB * KSPLIT * CI * CI];   // partial Grams (lower tri valid)
__device__ float g_spart[NB * KSPLIT * CI];        // partial row sums
__device__ float g_A[NB * CI * CI];                // folded matrix A'' (incl. +I)
__device__ float g_bvec[NB * CI];                  // folded bias b'

// =====================================================================
// Kernel 1: partial Gram (lower triangle only) via FFMA2.
// grid (KSPLIT, NB), 160 threads; threads 0..135 each own one lower-tri
// 8x8 tile of the 128x128 output; threads 0..127 do the loading.
// =====================================================================
__global__ void __launch_bounds__(160)
gram_kernel(const float* __restrict__ X)
{
    extern __shared__ float sm[];
    float* sdup  = sm;                 // [32][SDUP]  value duplicated pairs
    float* snorm = sm + 32 * SDUP;     // [32][SNORM] natural layout

    const int ks = blockIdx.x;
    const int bb = blockIdx.y;
    const float* Xb = X + (size_t)bb * CI * NPIX + ks * KCHUNK;
    const int t = threadIdx.x;

    // packed-triangle index -> (ti, tj), ti >= tj
    int ti = 0, tj = 0;
    const bool active = (t < 136);
    if (active) {
        ti = (int)((sqrtf(8.0f * (float)t + 1.0f) - 1.0f) * 0.5f);
        if ((ti + 1) * (ti + 2) / 2 <= t) ti++;
        if (ti * (ti + 1) / 2 > t) ti--;
        tj = t - ti * (ti + 1) / 2;
    }
    const int tr = ti * 8, tc = tj * 8;

    ull acc[8][4];
#pragma unroll
    for (int i = 0; i < 8; i++)
#pragma unroll
        for (int j = 0; j < 4; j++) acc[i][j] = 0ULL;
    float srow[8] = {0.f, 0.f, 0.f, 0.f, 0.f, 0.f, 0.f, 0.f};

    for (int ch = 0; ch < KCHUNK / 32; ++ch) {
        float4 buf[8];
        if (t < 128) {
            const float4* src = (const float4*)(Xb + (size_t)t * NPIX + ch * 32);
#pragma unroll
            for (int i = 0; i < 8; i++) buf[i] = src[i];
        }
        __syncthreads();   // previous chunk's compute done
        if (t < 128) {
#pragma unroll
            for (int i = 0; i < 8; i++) {
                float v[4] = {buf[i].x, buf[i].y, buf[i].z, buf[i].w};
#pragma unroll
                for (int q = 0; q < 4; q++) {
                    int kk = i * 4 + q;
                    snorm[kk * SNORM + t] = v[q];
                    *(float2*)&sdup[kk * SDUP + 2 * t] = make_float2(v[q], v[q]);
                }
            }
        }
        __syncthreads();

        if (active) {
#pragma unroll 2
            for (int k = 0; k < 32; k++) {
                const ulonglong2* ap = (const ulonglong2*)(sdup + k * SDUP + 2 * tr);
                ulonglong2 av0 = ap[0], av1 = ap[1], av2 = ap[2], av3 = ap[3];
                ull a[8] = {av0.x, av0.y, av1.x, av1.y, av2.x, av2.y, av3.x, av3.y};
                const ulonglong2* bp = (const ulonglong2*)(snorm + k * SNORM + tc);
                ulonglong2 bv0 = bp[0], bv1 = bp[1];
                ull b[4] = {bv0.x, bv0.y, bv1.x, bv1.y};
#pragma unroll
                for (int i = 0; i < 8; i++)
#pragma unroll
                    for (int j = 0; j < 4; j++) ffma2(acc[i][j], a[i], b[j]);
                if (tj == 0) {
#pragma unroll
                    for (int i = 0; i < 8; i++) srow[i] += lo32(a[i]);
                }
            }
        }
    }

    if (active) {
        float* P = g_Gpart + ((size_t)(bb * KSPLIT + ks)) * CI * CI;
#pragma unroll
        for (int i = 0; i < 8; i++) {
            float2 p0 = unpk(acc[i][0]), p1 = unpk(acc[i][1]);
            float2 p2 = unpk(acc[i][2]), p3 = unpk(acc[i][3]);
            float4 o0 = make_float4(p0.x, p0.y, p1.x, p1.y);
            float4 o1 = make_float4(p2.x, p2.y, p3.x, p3.y);
            float* dst = P + (size_t)(tr + i) * CI + tc;
            *(float4*)(dst)     = o0;
            *(float4*)(dst + 4) = o1;
        }
        if (tj == 0) {
#pragma unroll
            for (int i = 0; i < 8; i++)
                g_spart[(bb * KSPLIT + ks) * CI + tr + i] = srow[i];
        }
    }
}

// =====================================================================
// Kernel 2: per-batch chain of 128x128 GEMMs + softmax (FFMA2, reg-dup).
// 64 CTAs, 256 threads, 3 dynamic-smem 128xPAD buffers.
// mg128: W[i][j] = sum_e U[e][i]*V[e][j]
// =====================================================================
__device__ __forceinline__ void mg128(const float* U, const float* V,
                                      float* O, int t)
{
    const int tr = (t >> 4) << 3;
    const int tc = (t & 15) << 3;
    ull acc[8][4];
#pragma unroll
    for (int i = 0; i < 8; i++)
#pragma unroll
        for (int j = 0; j < 4; j++) acc[i][j] = 0ULL;

#pragma unroll 4
    for (int e = 0; e < 128; e++) {
        float4 u0 = *(const float4*)(U + e * PAD + tr);
        float4 u1 = *(const float4*)(U + e * PAD + tr + 4);
        ull a[8] = {dup2(u0.x), dup2(u0.y), dup2(u0.z), dup2(u0.w),
                    dup2(u1.x), dup2(u1.y), dup2(u1.z), dup2(u1.w)};
        const ulonglong2* bp = (const ulonglong2*)(V + e * PAD + tc);
        ulonglong2 bv0 = bp[0], bv1 = bp[1];
        ull b[4] = {bv0.x, bv0.y, bv1.x, bv1.y};
#pragma unroll
        for (int i = 0; i < 8; i++)
#pragma unroll
            for (int j = 0; j < 4; j++) ffma2(acc[i][j], a[i], b[j]);
    }
#pragma unroll
    for (int i = 0; i < 8; i++) {
        float2 p0 = unpk(acc[i][0]), p1 = unpk(acc[i][1]);
        float2 p2 = unpk(acc[i][2]), p3 = unpk(acc[i][3]);
        float* dst = O + (tr + i) * PAD + tc;
        *(float4*)(dst)     = make_float4(p0.x, p0.y, p1.x, p1.y);
        *(float4*)(dst + 4) = make_float4(p2.x, p2.y, p3.x, p3.y);
    }
}

__device__ __forceinline__ void mg128_final(const float* U, const float* V,
                                            float* gout, const float* scale, int t)
{
    const int tr = (t >> 4) << 3;
    const int tc = (t & 15) << 3;
    ull acc[8][4];
#pragma unroll
    for (int i = 0; i < 8; i++)
#pragma unroll
        for (int j = 0; j < 4; j++) acc[i][j] = 0ULL;

#pragma unroll 4
    for (int e = 0; e < 128; e++) {
        float4 u0 = *(const float4*)(U + e * PAD + tr);
        float4 u1 = *(const float4*)(U + e * PAD + tr + 4);
        ull a[8] = {dup2(u0.x), dup2(u0.y), dup2(u0.z), dup2(u0.w),
                    dup2(u1.x), dup2(u1.y), dup2(u1.z), dup2(u1.w)};
        const ulonglong2* bp = (const ulonglong2*)(V + e * PAD + tc);
        ulonglong2 bv0 = bp[0], bv1 = bp[1];
        ull b[4] = {bv0.x, bv0.y, bv1.x, bv1.y};
#pragma unroll
        for (int i = 0; i < 8; i++)
#pragma unroll
            for (int j = 0; j < 4; j++) ffma2(acc[i][j], a[i], b[j]);
    }
#pragma unroll
    for (int i = 0; i < 8; i++) {
        float sc = scale[tr + i];
        float vals[8];
        float2 p0 = unpk(acc[i][0]), p1 = unpk(acc[i][1]);
        float2 p2 = unpk(acc[i][2]), p3 = unpk(acc[i][3]);
        vals[0] = p0.x; vals[1] = p0.y; vals[2] = p1.x; vals[3] = p1.y;
        vals[4] = p2.x; vals[5] = p2.y; vals[6] = p3.x; vals[7] = p3.y;
#pragma unroll
        for (int j = 0; j < 8; j++) {
            int r = tr + i, c = tc + j;
            gout[r * CI + c] = sc * vals[j] + ((r == c) ? 1.0f : 0.0f);
        }
    }
}

__global__ void __launch_bounds__(256)
chain_kernel(const float* __restrict__ theta_w, const float* __restrict__ theta_b,
             const float* __restrict__ phi_w,   const float* __restrict__ phi_b,
             const float* __restrict__ g_w,     const float* __restrict__ g_b,
             const float* __restrict__ W_w,     const float* __restrict__ W_b,
             const float* __restrict__ bn_gamma, const float* __restrict__ bn_beta,
             const float* __restrict__ bn_mean,  const float* __restrict__ bn_var)
{
    extern __shared__ float dsm[];
    float* B0 = dsm;
    float* B1 = dsm + CI * PAD;
    float* B2 = dsm + 2 * CI * PAD;

    __shared__ float sv_s[CI], sv_u[CI], sv_q[CI], sv_tb[CI],
                     sv_gb[CI], sv_c[CI], sv_scale[CI];

    const int t  = threadIdx.x;
    const int bb = blockIdx.x;

    // --- stage G from lower-triangular partials (mirror on write) ---
    const float* Gp = g_Gpart + (size_t)bb * KSPLIT * CI * CI;
    for (int i = t; i < 8256; i += 256) {     // packed lower triangle incl diag
        int r = (int)((sqrtf(8.0f * (float)i + 1.0f) - 1.0f) * 0.5f);
        if ((r + 1) * (r + 2) / 2 <= i) r++;
        if (r * (r + 1) / 2 > i) r--;
        int c = i - r * (r + 1) / 2;
        float v = 0.f;
#pragma unroll
        for (int ks = 0; ks < KSPLIT; ks++) v += Gp[ks * CI * CI + r * CI + c];
        B0[r * PAD + c] = v;
        B0[c * PAD + r] = v;
    }
    if (t < CI) {
        float v = 0.f;
#pragma unroll
        for (int ks = 0; ks < KSPLIT; ks++) v += g_spart[(bb * KSPLIT + ks) * CI + t];
        sv_s[t]  = v;
        sv_tb[t] = theta_b[t];
        sv_gb[t] = g_b[t];
        sv_scale[t] = bn_gamma[t] * rsqrtf(bn_var[t] + 1e-5f);
    }
    // --- stage theta^T into B1 ---
    for (int idx = t; idx < CI * CI; idx += 256) {
        int r = idx >> 7, c = idx & 127;
        B1[c * PAD + r] = theta_w[idx];
    }
    __syncthreads();

    // v[d] = (theta_w s)[d];  q[d] = v[d] + N*theta_b[d]
    if (t < CI) {
        float v = 0.f;
#pragma unroll 8
        for (int e = 0; e < 128; e++) v += B1[e * PAD + t] * sv_s[e];
        sv_q[t] = v + 4096.0f * sv_tb[t];
    }
    __syncthreads();

    // step1: T1 = G theta^T   -> B2
    mg128(B0, B1, B2, t);
    __syncthreads();

    // stage phi^T into B0
    for (int idx = t; idx < CI * CI; idx += 256) {
        int r = idx >> 7, c = idx & 127;
        B0[c * PAD + r] = phi_w[idx];
    }
    __syncthreads();
    // u[c] = (phi_w s)[c]
    if (t < CI) {
        float v = 0.f;
#pragma unroll 8
        for (int e = 0; e < 128; e++) v += B0[e * PAD + t] * sv_s[e];
        sv_u[t] = v;
    }
    __syncthreads();

    // step2: L = phi T1  -> B1
    mg128(B0, B2, B1, t);
    __syncthreads();

    // softmax rows with rank-1 logit terms; write f^T into B2, cvec = f g_b
    if (t < CI) {
        float w1 = sv_u[t];
        float w2 = phi_b[t];
        float* row = B1 + t * PAD;
        float mx = -1e30f;
#pragma unroll 8
        for (int d = 0; d < 128; d++) {
            float v = row[d] + w1 * sv_tb[d] + w2 * sv_q[d];
            row[d] = v;
            mx = fmaxf(mx, v);
        }
        float ssum = 0.f;
#pragma unroll 8
        for (int d = 0; d < 128; d++) {
            float ev = expf(row[d] - mx);
            row[d] = ev;
            ssum += ev;
        }
        float inv = 1.0f / ssum;
        float cacc = 0.f;
#pragma unroll 8
        for (int d = 0; d < 128; d++) {
            float f = row[d] * inv;
            B2[d * PAD + t] = f;           // f^T
            cacc += f * sv_gb[d];
        }
        sv_c[t] = cacc;
    }
    __syncthreads();

    // stage g_w natural into B0
    for (int idx = t; idx < CI * CI; idx += 256)
        B0[(idx >> 7) * PAD + (idx & 127)] = g_w[idx];
    __syncthreads();

    // step4: M = f g_w  -> B1
    mg128(B2, B0, B1, t);
    __syncthreads();

    // stage W_w^T into B2
    for (int idx = t; idx < CI * CI; idx += 256) {
        int r = idx >> 7, c = idx & 127;
        B2[c * PAD + r] = W_w[idx];
    }
    __syncthreads();

    // bias: b' = scale*(W_w cvec + W_b) + (beta - mean*scale)
    if (t < CI) {
        float b0 = 0.f;
#pragma unroll 8
        for (int e = 0; e < 128; e++) b0 += B2[e * PAD + t] * sv_c[e];
        float sc = sv_scale[t];
        g_bvec[bb * CI + t] = sc * (b0 + W_b[t]) + bn_beta[t] - bn_mean[t] * sc;
    }

    // step5: A'' = diag(scale) * (W_w M) + I  -> global
    mg128_final(B2, B1, g_A + (size_t)bb * CI * CI, sv_scale, t);
}

// =====================================================================
// Kernel 3: Z = A'' X + b' 1^T  via FFMA2 (dup-A smem)
// grid (16, 64), 512 threads, 128x256 output tile
// =====================================================================
__global__ void __launch_bounds__(512)
apply_kernel(const float* __restrict__ X, float* __restrict__ Z)
{
    const int bb = blockIdx.y;
    const int n0 = blockIdx.x * 256;

    __shared__ float sATd[16][SDUP];   // A''^T chunk duplicated: [k][2r],[2r+1]
    __shared__ float sX[16][260];      // X chunk: [k][n]

    const int t   = threadIdx.x;
    const int tr  = (t >> 5) << 3;     // 16 thread-rows
    const int tcn = (t & 31) << 3;     // 32 thread-cols

    const float* Xb = X + (size_t)bb * CI * NPIX;
    const float* Ab = g_A + (size_t)bb * CI * CI;

    ull acc[8][4];
#pragma unroll
    for (int i = 0; i < 8; i++)
#pragma unroll
        for (int j = 0; j < 4; j++) acc[i][j] = 0ULL;

    for (int kc = 0; kc < 8; kc++) {
        float aBuf[4];
        float4 xBuf[2];
#pragma unroll
        for (int i = 0; i < 4; i++) {
            int li = t + i * 512;
            int r = li >> 4, kk = li & 15;
            aBuf[i] = Ab[r * CI + kc * 16 + kk];
        }
#pragma unroll
        for (int i = 0; i < 2; i++) {
            int li = t + i * 512;
            int row = li >> 6, c4 = li & 63;
            xBuf[i] = *(const float4*)(Xb + (size_t)(kc * 16 + row) * NPIX + n0 + c4 * 4);
        }
        __syncthreads();
#pragma unroll
        for (int i = 0; i < 4; i++) {
            int li = t + i * 512;
            int r = li >> 4, kk = li & 15;
            *(float2*)&sATd[kk][2 * r] = make_float2(aBuf[i], aBuf[i]);
        }
#pragma unroll
        for (int i = 0; i < 2; i++) {
            int li = t + i * 512;
            int row = li >> 6, c4 = li & 63;
            *(float4*)&sX[row][c4 * 4] = xBuf[i];
        }
        __syncthreads();

#pragma unroll 4
        for (int k = 0; k < 16; k++) {
            const ulonglong2* ap = (const ulonglong2*)&sATd[k][2 * tr];
            ulonglong2 av0 = ap[0], av1 = ap[1], av2 = ap[2], av3 = ap[3];
            ull a[8] = {av0.x, av0.y, av1.x, av1.y, av2.x, av2.y, av3.x, av3.y};
            const ulonglong2* bp = (const ulonglong2*)&sX[k][tcn];
            ulonglong2 bv0 = bp[0], bv1 = bp[1];
            ull b[4] = {bv0.x, bv0.y, bv1.x, bv1.y};
#pragma unroll
            for (int i = 0; i < 8; i++)
#pragma unroll
                for (int j = 0; j < 4; j++) ffma2(acc[i][j], a[i], b[j]);
        }
    }

#pragma unroll
    for (int i = 0; i < 8; i++) {
        float bias = g_bvec[bb * CI + tr + i];
        float2 p0 = unpk(acc[i][0]), p1 = unpk(acc[i][1]);
        float2 p2 = unpk(acc[i][2]), p3 = unpk(acc[i][3]);
        float4 o0 = make_float4(p0.x + bias, p0.y + bias, p1.x + bias, p1.y + bias);
        float4 o1 = make_float4(p2.x + bias, p2.y + bias, p3.x + bias, p3.y + bias);
        float* dst = Z + (size_t)bb * CI * NPIX + (size_t)(tr + i) * NPIX + n0 + tcn;
        *(float4*)(dst)     = o0;
        *(float4*)(dst + 4) = o1;
    }
}

// =====================================================================
extern "C" void kernel_launch(void* const* d_in, const int* in_sizes, int n_in,
                              void* d_out, int out_size)
{
    (void)in_sizes; (void)n_in; (void)out_size;
    const float* x        = (const float*)d_in[0];
    const float* theta_w  = (const float*)d_in[1];
    const float* theta_b  = (const float*)d_in[2];
    const float* phi_w    = (const float*)d_in[3];
    const float* phi_b    = (const float*)d_in[4];
    const float* g_w      = (const float*)d_in[5];
    const float* g_b      = (const float*)d_in[6];
    const float* W_w      = (const float*)d_in[7];
    const float* W_b      = (const float*)d_in[8];
    const float* bn_gamma = (const float*)d_in[9];
    const float* bn_beta  = (const float*)d_in[10];
    const float* bn_mean  = (const float*)d_in[11];
    const float* bn_var   = (const float*)d_in[12];
    float* out = (float*)d_out;

    const int smem_gram  = (32 * SDUP + 32 * SNORM) * (int)sizeof(float); // 50688
    const int smem_chain = 3 * CI * PAD * (int)sizeof(float);             // 202752
    cudaFuncSetAttribute(gram_kernel,
                         cudaFuncAttributeMaxDynamicSharedMemorySize, smem_gram);
    cudaFuncSetAttribute(chain_kernel,
                         cudaFuncAttributeMaxDynamicSharedMemorySize, smem_chain);

    gram_kernel<<<dim3(KSPLIT, NB), 160, smem_gram>>>(x);
    chain_kernel<<<NB, 256, smem_chain>>>(theta_w, theta_b, phi_w, phi_b,
                                          g_w, g_b, W_w, W_b,
                                          bn_gamma, bn_beta, bn_mean, bn_var);
    apply_kernel<<<dim3(NPIX / 256, NB), 512>>>(x, out);
}

// round 4
// speedup vs baseline: 1.1411x; 1.1411x over previous
#include <cuda_runtime.h>
#include <cuda_bf16.h>
#include <cstdint>
#include <math.h>

// Problem constants:
//  x: [16, 512, 64, 64] fp32 == [64 batches][128 ch][4096 px] contiguous
#define NB     64
#define CI     128
#define NPIX   4096
#define KSPLIT 8                 // gram K-split CTAs per batch (K=512 each)
#define PAD    132               // chain smem stride
#define SSTR   36                // gram smem stride (mult of 4, conflict-free frags)
#define ASTR   132               // apply smem stride

// ---------------- tf32 helpers ----------------
__device__ __forceinline__ void tf32split(float v, float& h, float& l) {
    uint32_t hb;
    asm("cvt.rna.tf32.f32 %0, %1;" : "=r"(hb) : "f"(v));
    h = __uint_as_float(hb);
    float lr = v - h;
    uint32_t lb;
    asm("cvt.rna.tf32.f32 %0, %1;" : "=r"(lb) : "f"(lr));
    l = __uint_as_float(lb);
}

// D += A(16x8,row) * B(8x8,col)   tf32 x f32-accum
__device__ __forceinline__ void mma8(float* d, const float* a, const float* b) {
    asm volatile(
        "mma.sync.aligned.m16n8k8.row.col.f32.tf32.tf32.f32 "
        "{%0,%1,%2,%3}, {%4,%5,%6,%7}, {%8,%9}, {%0,%1,%2,%3};"
        : "+f"(d[0]), "+f"(d[1]), "+f"(d[2]), "+f"(d[3])
        : "r"(__float_as_uint(a[0])), "r"(__float_as_uint(a[1])),
          "r"(__float_as_uint(a[2])), "r"(__float_as_uint(a[3])),
          "r"(__float_as_uint(b[0])), "r"(__float_as_uint(b[1])));
}

// ---------------- scratch ----------------
__device__ float g_Gpart[NB * KSPLIT * CI * CI];   // partial Grams
__device__ float g_spart[NB * KSPLIT * CI];        // partial row sums
__device__ float g_Ah[NB * CI * CI];               // A'' tf32-hi
__device__ float g_Al[NB * CI * CI];               // A'' tf32-lo
__device__ float g_bvec[NB * CI];                  // folded bias b'

// =====================================================================
// Kernel 1: partial Gram via mma.sync tf32x3.
// grid (KSPLIT, NB), 256 threads (8 warps). K=512 px, 16 chunks of 32 px.
// Warp w -> tile (rows (w>>2)*64, cols (w&3)*32); 4x4 m16n8 tiles each.
// =====================================================================
__global__ void __launch_bounds__(256)
gram_kernel(const float* __restrict__ X)
{
    __shared__ float sH[128][SSTR];
    __shared__ float sL[128][SSTR];
    __shared__ float sred[256];

    const int t = threadIdx.x;
    const int lane = t & 31, w = t >> 5;
    const int wr = (w >> 2) * 64, wc = (w & 3) * 32;
    const int qr = lane >> 2, qc = lane & 3;
    const int kc = blockIdx.x, bb = blockIdx.y;

    const float* Xb = X + (size_t)bb * CI * NPIX + (size_t)kc * 512;
    const int lrow = t >> 1, lseg = (t & 1) * 16;
    const float* Xr = Xb + (size_t)lrow * NPIX;

    float acc[4][4][4];
#pragma unroll
    for (int m = 0; m < 4; m++)
#pragma unroll
        for (int n = 0; n < 4; n++)
#pragma unroll
            for (int r = 0; r < 4; r++) acc[m][n][r] = 0.f;
    float mysum = 0.f;

    for (int ch = 0; ch < 16; ch++) {
        float4 v[4];
#pragma unroll
        for (int j = 0; j < 4; j++)
            v[j] = *(const float4*)(Xr + ch * 32 + lseg + 4 * j);

        __syncthreads();   // previous chunk's compute done
#pragma unroll
        for (int j = 0; j < 4; j++) {
            float h0, l0, h1, l1, h2, l2, h3, l3;
            tf32split(v[j].x, h0, l0); tf32split(v[j].y, h1, l1);
            tf32split(v[j].z, h2, l2); tf32split(v[j].w, h3, l3);
            *(float4*)&sH[lrow][lseg + 4 * j] = make_float4(h0, h1, h2, h3);
            *(float4*)&sL[lrow][lseg + 4 * j] = make_float4(l0, l1, l2, l3);
            mysum += v[j].x + v[j].y + v[j].z + v[j].w;
        }
        __syncthreads();

#pragma unroll
        for (int ks = 0; ks < 4; ks++) {
            const int k0 = ks * 8;
            float Ah[4][4], Al[4][4];
#pragma unroll
            for (int m = 0; m < 4; m++) {
                const int ar = wr + m * 16 + qr;
                Ah[m][0] = sH[ar][k0 + qc];       Ah[m][1] = sH[ar + 8][k0 + qc];
                Ah[m][2] = sH[ar][k0 + qc + 4];   Ah[m][3] = sH[ar + 8][k0 + qc + 4];
                Al[m][0] = sL[ar][k0 + qc];       Al[m][1] = sL[ar + 8][k0 + qc];
                Al[m][2] = sL[ar][k0 + qc + 4];   Al[m][3] = sL[ar + 8][k0 + qc + 4];
            }
#pragma unroll
            for (int n = 0; n < 4; n++) {
                const int br = wc + n * 8 + qr;
                float Bh[2], Bl[2];
                Bh[0] = sH[br][k0 + qc];  Bh[1] = sH[br][k0 + qc + 4];
                Bl[0] = sL[br][k0 + qc];  Bl[1] = sL[br][k0 + qc + 4];
#pragma unroll
                for (int m = 0; m < 4; m++) {
                    mma8(acc[m][n], Ah[m], Bh);
                    mma8(acc[m][n], Ah[m], Bl);
                    mma8(acc[m][n], Al[m], Bh);
                }
            }
        }
    }

    // row sums
    sred[t] = mysum;
    __syncthreads();
    if (t < 128)
        g_spart[(bb * KSPLIT + kc) * CI + t] = sred[2 * t] + sred[2 * t + 1];

    // write partial G
    float* P = g_Gpart + ((size_t)(bb * KSPLIT + kc)) * CI * CI;
#pragma unroll
    for (int m = 0; m < 4; m++) {
        const int r0 = wr + m * 16 + qr;
#pragma unroll
        for (int n = 0; n < 4; n++) {
            const int c0 = wc + n * 8 + qc * 2;
            *(float2*)(P + (size_t)r0 * CI + c0)       = make_float2(acc[m][n][0], acc[m][n][1]);
            *(float2*)(P + (size_t)(r0 + 8) * CI + c0) = make_float2(acc[m][n][2], acc[m][n][3]);
        }
    }
}

// =====================================================================
// Kernel 2: chain (fp32 CUDA cores, proven path) + tf32 split of A''.
// =====================================================================
__device__ __forceinline__ void mg128(const float* U, const float* V, float* O, int t)
{
    const int tr = (t >> 4) << 3;
    const int tc = (t & 15) << 3;
    float acc[8][8];
#pragma unroll
    for (int i = 0; i < 8; i++)
#pragma unroll
        for (int j = 0; j < 8; j++) acc[i][j] = 0.f;
#pragma unroll 4
    for (int e = 0; e < 128; e++) {
        float4 a0 = *(const float4*)(U + e * PAD + tr);
        float4 a1 = *(const float4*)(U + e * PAD + tr + 4);
        float4 b0 = *(const float4*)(V + e * PAD + tc);
        float4 b1 = *(const float4*)(V + e * PAD + tc + 4);
        float a[8] = {a0.x, a0.y, a0.z, a0.w, a1.x, a1.y, a1.z, a1.w};
        float b[8] = {b0.x, b0.y, b0.z, b0.w, b1.x, b1.y, b1.z, b1.w};
#pragma unroll
        for (int i = 0; i < 8; i++)
#pragma unroll
            for (int j = 0; j < 8; j++) acc[i][j] += a[i] * b[j];
    }
#pragma unroll
    for (int i = 0; i < 8; i++)
#pragma unroll
        for (int j = 0; j < 8; j++)
            O[(tr + i) * PAD + (tc + j)] = acc[i][j];
}

__device__ __forceinline__ void mg128_final(const float* U, const float* V,
                                            float* gAh, float* gAl,
                                            const float* scale, int t)
{
    const int tr = (t >> 4) << 3;
    const int tc = (t & 15) << 3;
    float acc[8][8];
#pragma unroll
    for (int i = 0; i < 8; i++)
#pragma unroll
        for (int j = 0; j < 8; j++) acc[i][j] = 0.f;
#pragma unroll 4
    for (int e = 0; e < 128; e++) {
        float4 a0 = *(const float4*)(U + e * PAD + tr);
        float4 a1 = *(const float4*)(U + e * PAD + tr + 4);
        float4 b0 = *(const float4*)(V + e * PAD + tc);
        float4 b1 = *(const float4*)(V + e * PAD + tc + 4);
        float a[8] = {a0.x, a0.y, a0.z, a0.w, a1.x, a1.y, a1.z, a1.w};
        float b[8] = {b0.x, b0.y, b0.z, b0.w, b1.x, b1.y, b1.z, b1.w};
#pragma unroll
        for (int i = 0; i < 8; i++)
#pragma unroll
            for (int j = 0; j < 8; j++) acc[i][j] += a[i] * b[j];
    }
#pragma unroll
    for (int i = 0; i < 8; i++) {
        float sc = scale[tr + i];
#pragma unroll
        for (int j = 0; j < 8; j++) {
            int r = tr + i, c = tc + j;
            float val = sc * acc[i][j] + ((r == c) ? 1.0f : 0.0f);
            float h, l;
            tf32split(val, h, l);
            gAh[r * CI + c] = h;
            gAl[r * CI + c] = l;
        }
    }
}

__global__ void __launch_bounds__(256)
chain_kernel(const float* __restrict__ theta_w, const float* __restrict__ theta_b,
             const float* __restrict__ phi_w,   const float* __restrict__ phi_b,
             const float* __restrict__ g_w,     const float* __restrict__ g_b,
             const float* __restrict__ W_w,     const float* __restrict__ W_b,
             const float* __restrict__ bn_gamma, const float* __restrict__ bn_beta,
             const float* __restrict__ bn_mean,  const float* __restrict__ bn_var)
{
    extern __shared__ float dsm[];
    float* B0 = dsm;
    float* B1 = dsm + CI * PAD;
    float* B2 = dsm + 2 * CI * PAD;

    __shared__ float sv_s[CI], sv_u[CI], sv_q[CI], sv_tb[CI],
                     sv_gb[CI], sv_c[CI], sv_scale[CI];

    const int t  = threadIdx.x;
    const int bb = blockIdx.x;

    const float* Gp = g_Gpart + (size_t)bb * KSPLIT * CI * CI;
    for (int idx = t; idx < CI * CI; idx += 256) {
        float v = 0.f;
#pragma unroll
        for (int ks = 0; ks < KSPLIT; ks++) v += Gp[ks * CI * CI + idx];
        B0[(idx >> 7) * PAD + (idx & 127)] = v;
    }
    if (t < CI) {
        float v = 0.f;
#pragma unroll
        for (int ks = 0; ks < KSPLIT; ks++) v += g_spart[(bb * KSPLIT + ks) * CI + t];
        sv_s[t]  = v;
        sv_tb[t] = theta_b[t];
        sv_gb[t] = g_b[t];
        sv_scale[t] = bn_gamma[t] * rsqrtf(bn_var[t] + 1e-5f);
    }
    for (int idx = t; idx < CI * CI; idx += 256) {
        int r = idx >> 7, c = idx & 127;
        B1[c * PAD + r] = theta_w[idx];
    }
    __syncthreads();

    if (t < CI) {
        float v = 0.f;
#pragma unroll 8
        for (int e = 0; e < 128; e++) v += B1[e * PAD + t] * sv_s[e];
        sv_q[t] = v + 4096.0f * sv_tb[t];
    }
    __syncthreads();

    mg128(B0, B1, B2, t);          // T1 = G theta^T
    __syncthreads();

    for (int idx = t; idx < CI * CI; idx += 256) {
        int r = idx >> 7, c = idx & 127;
        B0[c * PAD + r] = phi_w[idx];
    }
    __syncthreads();
    if (t < CI) {
        float v = 0.f;
#pragma unroll 8
        for (int e = 0; e < 128; e++) v += B0[e * PAD + t] * sv_s[e];
        sv_u[t] = v;
    }
    __syncthreads();

    mg128(B0, B2, B1, t);          // L = phi T1
    __syncthreads();

    if (t < CI) {
        float w1 = sv_u[t];
        float w2 = phi_b[t];
        float* rowp = B1 + t * PAD;
        float mx = -1e30f;
#pragma unroll 8
        for (int d = 0; d < 128; d++) {
            float v = rowp[d] + w1 * sv_tb[d] + w2 * sv_q[d];
            rowp[d] = v;
            mx = fmaxf(mx, v);
        }
        float ssum = 0.f;
#pragma unroll 8
        for (int d = 0; d < 128; d++) {
            float ev = expf(rowp[d] - mx);
            rowp[d] = ev;
            ssum += ev;
        }
        float inv = 1.0f / ssum;
        float cacc = 0.f;
#pragma unroll 8
        for (int d = 0; d < 128; d++) {
            float f = rowp[d] * inv;
            B2[d * PAD + t] = f;
            cacc += f * sv_gb[d];
        }
        sv_c[t] = cacc;
    }
    __syncthreads();

    for (int idx = t; idx < CI * CI; idx += 256)
        B0[(idx >> 7) * PAD + (idx & 127)] = g_w[idx];
    __syncthreads();

    mg128(B2, B0, B1, t);          // M = f g_w
    __syncthreads();

    for (int idx = t; idx < CI * CI; idx += 256) {
        int r = idx >> 7, c = idx & 127;
        B2[c * PAD + r] = W_w[idx];
    }
    __syncthreads();

    if (t < CI) {
        float b0 = 0.f;
#pragma unroll 8
        for (int e = 0; e < 128; e++) b0 += B2[e * PAD + t] * sv_c[e];
        float sc = sv_scale[t];
        g_bvec[bb * CI + t] = sc * (b0 + W_b[t]) + bn_beta[t] - bn_mean[t] * sc;
    }

    mg128_final(B2, B1, g_Ah + (size_t)bb * CI * CI, g_Al + (size_t)bb * CI * CI,
                sv_scale, t);
}

// =====================================================================
// Kernel 3: Z = A'' X + b' via mma.sync tf32x3.
// grid (NPIX/512, NB), 256 threads. A'' hi/lo resident in smem; X chunks
// of [32 in_ch x 128 px] split per px-sub-block. Warp tile 64ch x 32px.
// =====================================================================
#define AP_SMEM ((2 * 128 * ASTR + 2 * 32 * ASTR) * 4)   // 168960 B

__global__ void __launch_bounds__(256)
apply_kernel(const float* __restrict__ X, float* __restrict__ Z)
{
    extern __shared__ float asm_[];
    float* sAh = asm_;                    // [128][ASTR]
    float* sAl = sAh + 128 * ASTR;
    float* sXh = sAl + 128 * ASTR;        // [32][ASTR]
    float* sXl = sXh + 32 * ASTR;

    const int t = threadIdx.x;
    const int lane = t & 31, w = t >> 5;
    const int wr = (w >> 2) * 64, wc = (w & 3) * 32;
    const int qr = lane >> 2, qc = lane & 3;
    const int bb = blockIdx.y;
    const int n0 = blockIdx.x * 512;

    // ---- load A'' hi/lo resident ----
    {
        const int row = t >> 1, seg = (t & 1) * 64;
        const float* Ah = g_Ah + (size_t)bb * CI * CI + row * CI + seg;
        const float* Al = g_Al + (size_t)bb * CI * CI + row * CI + seg;
#pragma unroll
        for (int j = 0; j < 16; j++) {
            *(float4*)&sAh[row * ASTR + seg + 4 * j] = *(const float4*)(Ah + 4 * j);
            *(float4*)&sAl[row * ASTR + seg + 4 * j] = *(const float4*)(Al + 4 * j);
        }
    }

    // per-thread biases (fixed output rows)
    float bias[4][2];
#pragma unroll
    for (int m = 0; m < 4; m++) {
        bias[m][0] = g_bvec[bb * CI + wr + m * 16 + qr];
        bias[m][1] = g_bvec[bb * CI + wr + m * 16 + qr + 8];
    }

    const float* Xb = X + (size_t)bb * CI * NPIX;
    float* Zb = Z + (size_t)bb * CI * NPIX;

    const int lch = t >> 3, lseg = (t & 7) * 16;   // X chunk loader

    for (int sub = 0; sub < 4; sub++) {
        const int px0 = n0 + sub * 128;
        float acc[4][4][4];
#pragma unroll
        for (int m = 0; m < 4; m++)
#pragma unroll
            for (int n = 0; n < 4; n++)
#pragma unroll
                for (int r = 0; r < 4; r++) acc[m][n][r] = 0.f;

        for (int kcu = 0; kcu < 4; kcu++) {
            float4 v[4];
#pragma unroll
            for (int j = 0; j < 4; j++)
                v[j] = *(const float4*)(Xb + (size_t)(kcu * 32 + lch) * NPIX + px0 + lseg + 4 * j);

            __syncthreads();   // previous compute done
#pragma unroll
            for (int j = 0; j < 4; j++) {
                float h0, l0, h1, l1, h2, l2, h3, l3;
                tf32split(v[j].x, h0, l0); tf32split(v[j].y, h1, l1);
                tf32split(v[j].z, h2, l2); tf32split(v[j].w, h3, l3);
                *(float4*)&sXh[lch * ASTR + lseg + 4 * j] = make_float4(h0, h1, h2, h3);
                *(float4*)&sXl[lch * ASTR + lseg + 4 * j] = make_float4(l0, l1, l2, l3);
            }
            __syncthreads();

#pragma unroll
            for (int ks = 0; ks < 4; ks++) {
                const int kl = ks * 8;              // k within chunk
                const int kg = kcu * 32 + kl;       // global k (A col)
                float Ah[4][4], Al[4][4];
#pragma unroll
                for (int m = 0; m < 4; m++) {
                    const int ar = wr + m * 16 + qr;
                    Ah[m][0] = sAh[ar * ASTR + kg + qc];
                    Ah[m][1] = sAh[(ar + 8) * ASTR + kg + qc];
                    Ah[m][2] = sAh[ar * ASTR + kg + qc + 4];
                    Ah[m][3] = sAh[(ar + 8) * ASTR + kg + qc + 4];
                    Al[m][0] = sAl[ar * ASTR + kg + qc];
                    Al[m][1] = sAl[(ar + 8) * ASTR + kg + qc];
                    Al[m][2] = sAl[ar * ASTR + kg + qc + 4];
                    Al[m][3] = sAl[(ar + 8) * ASTR + kg + qc + 4];
                }
#pragma unroll
                for (int n = 0; n < 4; n++) {
                    const int bpx = wc + n * 8 + qr;
                    float Bh[2], Bl[2];
                    Bh[0] = sXh[(kl + qc) * ASTR + bpx];
                    Bh[1] = sXh[(kl + qc + 4) * ASTR + bpx];
                    Bl[0] = sXl[(kl + qc) * ASTR + bpx];
                    Bl[1] = sXl[(kl + qc + 4) * ASTR + bpx];
#pragma unroll
                    for (int m = 0; m < 4; m++) {
                        mma8(acc[m][n], Ah[m], Bh);
                        mma8(acc[m][n], Ah[m], Bl);
                        mma8(acc[m][n], Al[m], Bh);
                    }
                }
            }
        }

        // epilogue: bias + store
#pragma unroll
        for (int m = 0; m < 4; m++) {
            const int r0 = wr + m * 16 + qr;
#pragma unroll
            for (int n = 0; n < 4; n++) {
                const int c0 = px0 + wc + n * 8 + qc * 2;
                *(float2*)(Zb + (size_t)r0 * NPIX + c0) =
                    make_float2(acc[m][n][0] + bias[m][0], acc[m][n][1] + bias[m][0]);
                *(float2*)(Zb + (size_t)(r0 + 8) * NPIX + c0) =
                    make_float2(acc[m][n][2] + bias[m][1], acc[m][n][3] + bias[m][1]);
            }
        }
        __syncthreads();   // keep sX stable until all warps finished epilogue
    }
}

// =====================================================================
extern "C" void kernel_launch(void* const* d_in, const int* in_sizes, int n_in,
                              void* d_out, int out_size)
{
    (void)in_sizes; (void)n_in; (void)out_size;
    const float* x        = (const float*)d_in[0];
    const float* theta_w  = (const float*)d_in[1];
    const float* theta_b  = (const float*)d_in[2];
    const float* phi_w    = (const float*)d_in[3];
    const float* phi_b    = (const float*)d_in[4];
    const float* g_w      = (const float*)d_in[5];
    const float* g_b      = (const float*)d_in[6];
    const float* W_w      = (const float*)d_in[7];
    const float* W_b      = (const float*)d_in[8];
    const float* bn_gamma = (const float*)d_in[9];
    const float* bn_beta  = (const float*)d_in[10];
    const float* bn_mean  = (const float*)d_in[11];
    const float* bn_var   = (const float*)d_in[12];
    float* out = (float*)d_out;

    const int smem_chain = 3 * CI * PAD * (int)sizeof(float);  // 202752
    cudaFuncSetAttribute(chain_kernel,
                         cudaFuncAttributeMaxDynamicSharedMemorySize, smem_chain);
    cudaFuncSetAttribute(apply_kernel,
                         cudaFuncAttributeMaxDynamicSharedMemorySize, AP_SMEM);

    gram_kernel<<<dim3(KSPLIT, NB), 256>>>(x);
    chain_kernel<<<NB, 256, smem_chain>>>(theta_w, theta_b, phi_w, phi_b,
                                          g_w, g_b, W_w, W_b,
                                          bn_gamma, bn_beta, bn_mean, bn_var);
    apply_kernel<<<dim3(NPIX / 512, NB), 256, AP_SMEM>>>(x, out);
}

// round 5
// speedup vs baseline: 1.2444x; 1.0906x over previous
#include <cuda_runtime.h>
#include <cuda_bf16.h>
#include <cstdint>
#include <math.h>

// Problem constants:
//  x: [16, 512, 64, 64] fp32 == [64 batches][128 ch][4096 px] contiguous
#define NB     64
#define CI     128
#define NPIX   4096
#define KSPLIT 8                 // gram K-split CTAs per batch (K=512 each)
#define PAD    132               // chain smem stride
#define GSTR   20                // gram smem stride (16 + 4)
#define ASTR   132               // apply smem stride

// ---------------- tf32 helpers ----------------
__device__ __forceinline__ void tf32split(float v, float& h, float& l) {
    uint32_t hb;
    asm("cvt.rna.tf32.f32 %0, %1;" : "=r"(hb) : "f"(v));
    h = __uint_as_float(hb);
    float lr = v - h;
    uint32_t lb;
    asm("cvt.rna.tf32.f32 %0, %1;" : "=r"(lb) : "f"(lr));
    l = __uint_as_float(lb);
}

// D += A(16x8,row) * B(8x8,col)   tf32 x f32-accum
__device__ __forceinline__ void mma8(float* d, const float* a, const float* b) {
    asm volatile(
        "mma.sync.aligned.m16n8k8.row.col.f32.tf32.tf32.f32 "
        "{%0,%1,%2,%3}, {%4,%5,%6,%7}, {%8,%9}, {%0,%1,%2,%3};"
        : "+f"(d[0]), "+f"(d[1]), "+f"(d[2]), "+f"(d[3])
        : "r"(__float_as_uint(a[0])), "r"(__float_as_uint(a[1])),
          "r"(__float_as_uint(a[2])), "r"(__float_as_uint(a[3])),
          "r"(__float_as_uint(b[0])), "r"(__float_as_uint(b[1])));
}

// ---------------- scratch ----------------
__device__ float g_Gpart[NB * KSPLIT * CI * CI];   // partial E (G = (E+E^T)/2)
__device__ float g_spart[NB * KSPLIT * CI];        // partial row sums
__device__ float g_Ah[NB * CI * CI];               // A'' tf32-hi
__device__ float g_Al[NB * CI * CI];               // A'' tf32-lo
__device__ float g_bvec[NB * CI];                  // folded bias b'

// =====================================================================
// Kernel 1: partial E = H H^T + H (2L)^T via mma.sync (2 products).
// grid (KSPLIT, NB), 256 threads. K=512 px, 32 chunks of 16 px,
// double-buffered smem, one barrier per chunk.
// =====================================================================
__device__ __forceinline__ float gram_split(float4 v0, float4 v1,
                                            float* bH, float* bL, int lrow, int lseg)
{
    float va[8] = {v0.x, v0.y, v0.z, v0.w, v1.x, v1.y, v1.z, v1.w};
    float h[8], l[8];
#pragma unroll
    for (int j = 0; j < 8; j++) {
        tf32split(va[j], h[j], l[j]);
        l[j] *= 2.0f;
    }
    *(float4*)&bH[lrow * GSTR + lseg]     = make_float4(h[0], h[1], h[2], h[3]);
    *(float4*)&bH[lrow * GSTR + lseg + 4] = make_float4(h[4], h[5], h[6], h[7]);
    *(float4*)&bL[lrow * GSTR + lseg]     = make_float4(l[0], l[1], l[2], l[3]);
    *(float4*)&bL[lrow * GSTR + lseg + 4] = make_float4(l[4], l[5], l[6], l[7]);
    return va[0] + va[1] + va[2] + va[3] + va[4] + va[5] + va[6] + va[7];
}

__global__ void __launch_bounds__(256, 2)
gram_kernel(const float* __restrict__ X)
{
    __shared__ float sH[2][128 * GSTR];
    __shared__ float sL[2][128 * GSTR];
    __shared__ float sred[256];

    const int t = threadIdx.x;
    const int lane = t & 31, w = t >> 5;
    const int wr = (w >> 2) * 64, wc = (w & 3) * 32;
    const int qr = lane >> 2, qc = lane & 3;
    const int kc = blockIdx.x, bb = blockIdx.y;

    const float* Xb = X + (size_t)bb * CI * NPIX + (size_t)kc * 512;
    const int lrow = t >> 1, lseg = (t & 1) * 8;
    const float* Xr = Xb + (size_t)lrow * NPIX;

    float acc[4][4][4];
#pragma unroll
    for (int m = 0; m < 4; m++)
#pragma unroll
        for (int n = 0; n < 4; n++)
#pragma unroll
            for (int r = 0; r < 4; r++) acc[m][n][r] = 0.f;
    float mysum = 0.f;

    // preload chunk 0
    {
        float4 v0 = *(const float4*)(Xr + lseg);
        float4 v1 = *(const float4*)(Xr + lseg + 4);
        mysum += gram_split(v0, v1, sH[0], sL[0], lrow, lseg);
    }
    __syncthreads();

    for (int ch = 0; ch < 32; ch++) {
        const int b = ch & 1;
        float4 n0, n1;
        if (ch < 31) {
            n0 = *(const float4*)(Xr + (ch + 1) * 16 + lseg);
            n1 = *(const float4*)(Xr + (ch + 1) * 16 + lseg + 4);
        }

        const float* cH = sH[b];
        const float* cL = sL[b];
#pragma unroll
        for (int ks = 0; ks < 2; ks++) {
            const int k0 = ks * 8;
            float Ah[4][4];
#pragma unroll
            for (int m = 0; m < 4; m++) {
                const int ar = wr + m * 16 + qr;
                Ah[m][0] = cH[ar * GSTR + k0 + qc];
                Ah[m][1] = cH[(ar + 8) * GSTR + k0 + qc];
                Ah[m][2] = cH[ar * GSTR + k0 + qc + 4];
                Ah[m][3] = cH[(ar + 8) * GSTR + k0 + qc + 4];
            }
#pragma unroll
            for (int n = 0; n < 4; n++) {
                const int br = wc + n * 8 + qr;
                float Bh[2], Bl[2];
                Bh[0] = cH[br * GSTR + k0 + qc];
                Bh[1] = cH[br * GSTR + k0 + qc + 4];
                Bl[0] = cL[br * GSTR + k0 + qc];
                Bl[1] = cL[br * GSTR + k0 + qc + 4];
#pragma unroll
                for (int m = 0; m < 4; m++) {
                    mma8(acc[m][n], Ah[m], Bh);
                    mma8(acc[m][n], Ah[m], Bl);
                }
            }
        }

        if (ch < 31)
            mysum += gram_split(n0, n1, sH[b ^ 1], sL[b ^ 1], lrow, lseg);
        __syncthreads();
    }

    // row sums
    sred[t] = mysum;
    __syncthreads();
    if (t < 128)
        g_spart[(bb * KSPLIT + kc) * CI + t] = sred[2 * t] + sred[2 * t + 1];

    // write partial E
    float* P = g_Gpart + ((size_t)(bb * KSPLIT + kc)) * CI * CI;
#pragma unroll
    for (int m = 0; m < 4; m++) {
        const int r0 = wr + m * 16 + qr;
#pragma unroll
        for (int n = 0; n < 4; n++) {
            const int c0 = wc + n * 8 + qc * 2;
            *(float2*)(P + (size_t)r0 * CI + c0)       = make_float2(acc[m][n][0], acc[m][n][1]);
            *(float2*)(P + (size_t)(r0 + 8) * CI + c0) = make_float2(acc[m][n][2], acc[m][n][3]);
        }
    }
}

// =====================================================================
// Kernel 2: chain (fp32 CUDA cores) + tf32 split of A''.
// =====================================================================
__device__ __forceinline__ void mg128(const float* U, const float* V, float* O, int t)
{
    const int tr = (t >> 4) << 3;
    const int tc = (t & 15) << 3;
    float acc[8][8];
#pragma unroll
    for (int i = 0; i < 8; i++)
#pragma unroll
        for (int j = 0; j < 8; j++) acc[i][j] = 0.f;
#pragma unroll 4
    for (int e = 0; e < 128; e++) {
        float4 a0 = *(const float4*)(U + e * PAD + tr);
        float4 a1 = *(const float4*)(U + e * PAD + tr + 4);
        float4 b0 = *(const float4*)(V + e * PAD + tc);
        float4 b1 = *(const float4*)(V + e * PAD + tc + 4);
        float a[8] = {a0.x, a0.y, a0.z, a0.w, a1.x, a1.y, a1.z, a1.w};
        float b[8] = {b0.x, b0.y, b0.z, b0.w, b1.x, b1.y, b1.z, b1.w};
#pragma unroll
        for (int i = 0; i < 8; i++)
#pragma unroll
            for (int j = 0; j < 8; j++) acc[i][j] += a[i] * b[j];
    }
#pragma unroll
    for (int i = 0; i < 8; i++)
#pragma unroll
        for (int j = 0; j < 8; j++)
            O[(tr + i) * PAD + (tc + j)] = acc[i][j];
}

__device__ __forceinline__ void mg128_final(const float* U, const float* V,
                                            float* gAh, float* gAl,
                                            const float* scale, int t)
{
    const int tr = (t >> 4) << 3;
    const int tc = (t & 15) << 3;
    float acc[8][8];
#pragma unroll
    for (int i = 0; i < 8; i++)
#pragma unroll
        for (int j = 0; j < 8; j++) acc[i][j] = 0.f;
#pragma unroll 4
    for (int e = 0; e < 128; e++) {
        float4 a0 = *(const float4*)(U + e * PAD + tr);
        float4 a1 = *(const float4*)(U + e * PAD + tr + 4);
        float4 b0 = *(const float4*)(V + e * PAD + tc);
        float4 b1 = *(const float4*)(V + e * PAD + tc + 4);
        float a[8] = {a0.x, a0.y, a0.z, a0.w, a1.x, a1.y, a1.z, a1.w};
        float b[8] = {b0.x, b0.y, b0.z, b0.w, b1.x, b1.y, b1.z, b1.w};
#pragma unroll
        for (int i = 0; i < 8; i++)
#pragma unroll
            for (int j = 0; j < 8; j++) acc[i][j] += a[i] * b[j];
    }
#pragma unroll
    for (int i = 0; i < 8; i++) {
        float sc = scale[tr + i];
#pragma unroll
        for (int j = 0; j < 8; j++) {
            int r = tr + i, c = tc + j;
            float val = sc * acc[i][j] + ((r == c) ? 1.0f : 0.0f);
            float h, l;
            tf32split(val, h, l);
            gAh[r * CI + c] = h;
            gAl[r * CI + c] = l;
        }
    }
}

__global__ void __launch_bounds__(256)
chain_kernel(const float* __restrict__ theta_w, const float* __restrict__ theta_b,
             const float* __restrict__ phi_w,   const float* __restrict__ phi_b,
             const float* __restrict__ g_w,     const float* __restrict__ g_b,
             const float* __restrict__ W_w,     const float* __restrict__ W_b,
             const float* __restrict__ bn_gamma, const float* __restrict__ bn_beta,
             const float* __restrict__ bn_mean,  const float* __restrict__ bn_var)
{
    extern __shared__ float dsm[];
    float* B0 = dsm;
    float* B1 = dsm + CI * PAD;
    float* B2 = dsm + 2 * CI * PAD;

    __shared__ float sv_s[CI], sv_u[CI], sv_q[CI], sv_tb[CI],
                     sv_gb[CI], sv_c[CI], sv_scale[CI];

    const int t  = threadIdx.x;
    const int bb = blockIdx.x;

    // --- stage S = sum_ks E_ks into B2 (coalesced); theta^T into B1 ---
    const float* Gp = g_Gpart + (size_t)bb * KSPLIT * CI * CI;
    for (int idx = t; idx < CI * CI; idx += 256) {
        float v = 0.f;
#pragma unroll
        for (int ks = 0; ks < KSPLIT; ks++) v += Gp[ks * CI * CI + idx];
        B2[(idx >> 7) * PAD + (idx & 127)] = v;
    }
    if (t < CI) {
        float v = 0.f;
#pragma unroll
        for (int ks = 0; ks < KSPLIT; ks++) v += g_spart[(bb * KSPLIT + ks) * CI + t];
        sv_s[t]  = v;
        sv_tb[t] = theta_b[t];
        sv_gb[t] = g_b[t];
        sv_scale[t] = bn_gamma[t] * rsqrtf(bn_var[t] + 1e-5f);
    }
    for (int idx = t; idx < CI * CI; idx += 256) {
        int r = idx >> 7, c = idx & 127;
        B1[c * PAD + r] = theta_w[idx];
    }
    __syncthreads();

    // --- symmetrize: G = (S + S^T)/2 into B0;  q from theta^T ---
    for (int idx = t; idx < CI * CI; idx += 256) {
        int r = idx >> 7, c = idx & 127;
        B0[r * PAD + c] = 0.5f * (B2[r * PAD + c] + B2[c * PAD + r]);
    }
    if (t < CI) {
        float v = 0.f;
#pragma unroll 8
        for (int e = 0; e < 128; e++) v += B1[e * PAD + t] * sv_s[e];
        sv_q[t] = v + 4096.0f * sv_tb[t];
    }
    __syncthreads();

    mg128(B0, B1, B2, t);          // T1 = G theta^T
    __syncthreads();

    for (int idx = t; idx < CI * CI; idx += 256) {
        int r = idx >> 7, c = idx & 127;
        B0[c * PAD + r] = phi_w[idx];
    }
    __syncthreads();
    if (t < CI) {
        float v = 0.f;
#pragma unroll 8
        for (int e = 0; e < 128; e++) v += B0[e * PAD + t] * sv_s[e];
        sv_u[t] = v;
    }
    __syncthreads();

    mg128(B0, B2, B1, t);          // L = phi T1
    __syncthreads();

    if (t < CI) {
        float w1 = sv_u[t];
        float w2 = phi_b[t];
        float* rowp = B1 + t * PAD;
        float mx = -1e30f;
#pragma unroll 8
        for (int d = 0; d < 128; d++) {
            float v = rowp[d] + w1 * sv_tb[d] + w2 * sv_q[d];
            rowp[d] = v;
            mx = fmaxf(mx, v);
        }
        float ssum = 0.f;
#pragma unroll 8
        for (int d = 0; d < 128; d++) {
            float ev = expf(rowp[d] - mx);
            rowp[d] = ev;
            ssum += ev;
        }
        float inv = 1.0f / ssum;
        float cacc = 0.f;
#pragma unroll 8
        for (int d = 0; d < 128; d++) {
            float f = rowp[d] * inv;
            B2[d * PAD + t] = f;
            cacc += f * sv_gb[d];
        }
        sv_c[t] = cacc;
    }
    __syncthreads();

    for (int idx = t; idx < CI * CI; idx += 256)
        B0[(idx >> 7) * PAD + (idx & 127)] = g_w[idx];
    __syncthreads();

    mg128(B2, B0, B1, t);          // M = f g_w
    __syncthreads();

    for (int idx = t; idx < CI * CI; idx += 256) {
        int r = idx >> 7, c = idx & 127;
        B2[c * PAD + r] = W_w[idx];
    }
    __syncthreads();

    if (t < CI) {
        float b0 = 0.f;
#pragma unroll 8
        for (int e = 0; e < 128; e++) b0 += B2[e * PAD + t] * sv_c[e];
        float sc = sv_scale[t];
        g_bvec[bb * CI + t] = sc * (b0 + W_b[t]) + bn_beta[t] - bn_mean[t] * sc;
    }

    mg128_final(B2, B1, g_Ah + (size_t)bb * CI * CI, g_Al + (size_t)bb * CI * CI,
                sv_scale, t);
}

// =====================================================================
// Kernel 3: Z = A'' X + b' via mma.sync tf32x3, pipelined X chunks.
// grid (NPIX/512, NB), 256 threads. A'' hi/lo resident in smem;
// 16 chunks of [32 in_ch x 128 px], double-buffered, 1 barrier/chunk.
// =====================================================================
#define AP_SMEM ((2 * 128 * ASTR + 4 * 32 * ASTR) * 4)   // 202752 B

__global__ void __launch_bounds__(256)
apply_kernel(const float* __restrict__ X, float* __restrict__ Z)
{
    extern __shared__ float apsm[];
    float* sAh = apsm;                        // [128][ASTR]
    float* sAl = sAh + 128 * ASTR;
    float* sXh[2] = {sAl + 128 * ASTR, sAl + 128 * ASTR + 32 * ASTR};
    float* sXl[2] = {sAl + 128 * ASTR + 2 * 32 * ASTR,
                     sAl + 128 * ASTR + 3 * 32 * ASTR};

    const int t = threadIdx.x;
    const int lane = t & 31, w = t >> 5;
    const int wr = (w >> 2) * 64, wc = (w & 3) * 32;
    const int qr = lane >> 2, qc = lane & 3;
    const int bb = blockIdx.y;
    const int n0 = blockIdx.x * 512;

    // ---- load A'' hi/lo resident ----
    {
        const int row = t >> 1, seg = (t & 1) * 64;
        const float* Ah = g_Ah + (size_t)bb * CI * CI + row * CI + seg;
        const float* Al = g_Al + (size_t)bb * CI * CI + row * CI + seg;
#pragma unroll
        for (int j = 0; j < 16; j++) {
            *(float4*)&sAh[row * ASTR + seg + 4 * j] = *(const float4*)(Ah + 4 * j);
            *(float4*)&sAl[row * ASTR + seg + 4 * j] = *(const float4*)(Al + 4 * j);
        }
    }

    float bias[4][2];
#pragma unroll
    for (int m = 0; m < 4; m++) {
        bias[m][0] = g_bvec[bb * CI + wr + m * 16 + qr];
        bias[m][1] = g_bvec[bb * CI + wr + m * 16 + qr + 8];
    }

    const float* Xb = X + (size_t)bb * CI * NPIX;
    float* Zb = Z + (size_t)bb * CI * NPIX;

    const int lch = t >> 3, lseg = (t & 7) * 16;

    float acc[4][4][4];
#pragma unroll
    for (int m = 0; m < 4; m++)
#pragma unroll
        for (int n = 0; n < 4; n++)
#pragma unroll
            for (int r = 0; r < 4; r++) acc[m][n][r] = 0.f;

    // preload chunk 0 (kcu=0, sub=0)
    {
        const float* src = Xb + (size_t)lch * NPIX + n0 + lseg;
#pragma unroll
        for (int j = 0; j < 4; j++) {
            float4 v = *(const float4*)(src + 4 * j);
            float h0, l0, h1, l1, h2, l2, h3, l3;
            tf32split(v.x, h0, l0); tf32split(v.y, h1, l1);
            tf32split(v.z, h2, l2); tf32split(v.w, h3, l3);
            *(float4*)&sXh[0][lch * ASTR + lseg + 4 * j] = make_float4(h0, h1, h2, h3);
            *(float4*)&sXl[0][lch * ASTR + lseg + 4 * j] = make_float4(l0, l1, l2, l3);
        }
    }
    __syncthreads();

    for (int g = 0; g < 16; g++) {
        const int b = g & 1;
        float4 nx[4];
        if (g < 15) {
            const int kcu = (g + 1) & 3, sub = (g + 1) >> 2;
            const float* src = Xb + (size_t)(kcu * 32 + lch) * NPIX + n0 + sub * 128 + lseg;
#pragma unroll
            for (int j = 0; j < 4; j++) nx[j] = *(const float4*)(src + 4 * j);
        }

        // MMA on buffer b (K rows kcu*32 .. +32)
        const int kcu = g & 3;
#pragma unroll
        for (int ks = 0; ks < 4; ks++) {
            const int kl = ks * 8;
            const int kg = kcu * 32 + kl;
            float Ahf[4][4], Alf[4][4];
#pragma unroll
            for (int m = 0; m < 4; m++) {
                const int ar = wr + m * 16 + qr;
                Ahf[m][0] = sAh[ar * ASTR + kg + qc];
                Ahf[m][1] = sAh[(ar + 8) * ASTR + kg + qc];
                Ahf[m][2] = sAh[ar * ASTR + kg + qc + 4];
                Ahf[m][3] = sAh[(ar + 8) * ASTR + kg + qc + 4];
                Alf[m][0] = sAl[ar * ASTR + kg + qc];
                Alf[m][1] = sAl[(ar + 8) * ASTR + kg + qc];
                Alf[m][2] = sAl[ar * ASTR + kg + qc + 4];
                Alf[m][3] = sAl[(ar + 8) * ASTR + kg + qc + 4];
            }
#pragma unroll
            for (int n = 0; n < 4; n++) {
                const int bpx = wc + n * 8 + qr;
                float Bh[2], Bl[2];
                Bh[0] = sXh[b][(kl + qc) * ASTR + bpx];
                Bh[1] = sXh[b][(kl + qc + 4) * ASTR + bpx];
                Bl[0] = sXl[b][(kl + qc) * ASTR + bpx];
                Bl[1] = sXl[b][(kl + qc + 4) * ASTR + bpx];
#pragma unroll
                for (int m = 0; m < 4; m++) {
                    mma8(acc[m][n], Ahf[m], Bh);
                    mma8(acc[m][n], Ahf[m], Bl);
                    mma8(acc[m][n], Alf[m], Bh);
                }
            }
        }

        if (g < 15) {
#pragma unroll
            for (int j = 0; j < 4; j++) {
                float4 v = nx[j];
                float h0, l0, h1, l1, h2, l2, h3, l3;
                tf32split(v.x, h0, l0); tf32split(v.y, h1, l1);
                tf32split(v.z, h2, l2); tf32split(v.w, h3, l3);
                *(float4*)&sXh[b ^ 1][lch * ASTR + lseg + 4 * j] = make_float4(h0, h1, h2, h3);
                *(float4*)&sXl[b ^ 1][lch * ASTR + lseg + 4 * j] = make_float4(l0, l1, l2, l3);
            }
        }
        __syncthreads();

        // epilogue at sub boundary (after barrier; touches only regs/gmem)
        if ((g & 3) == 3) {
            const int px0 = n0 + (g >> 2) * 128;
#pragma unroll
            for (int m = 0; m < 4; m++) {
                const int r0 = wr + m * 16 + qr;
#pragma unroll
                for (int n = 0; n < 4; n++) {
                    const int c0 = px0 + wc + n * 8 + qc * 2;
                    *(float2*)(Zb + (size_t)r0 * NPIX + c0) =
                        make_float2(acc[m][n][0] + bias[m][0], acc[m][n][1] + bias[m][0]);
                    *(float2*)(Zb + (size_t)(r0 + 8) * NPIX + c0) =
                        make_float2(acc[m][n][2] + bias[m][1], acc[m][n][3] + bias[m][1]);
                }
            }
#pragma unroll
            for (int m = 0; m < 4; m++)
#pragma unroll
                for (int n = 0; n < 4; n++)
#pragma unroll
                    for (int r = 0; r < 4; r++) acc[m][n][r] = 0.f;
        }
    }
}

// =====================================================================
extern "C" void kernel_launch(void* const* d_in, const int* in_sizes, int n_in,
                              void* d_out, int out_size)
{
    (void)in_sizes; (void)n_in; (void)out_size;
    const float* x        = (const float*)d_in[0];
    const float* theta_w  = (const float*)d_in[1];
    const float* theta_b  = (const float*)d_in[2];
    const float* phi_w    = (const float*)d_in[3];
    const float* phi_b    = (const float*)d_in[4];
    const float* g_w      = (const float*)d_in[5];
    const float* g_b      = (const float*)d_in[6];
    const float* W_w      = (const float*)d_in[7];
    const float* W_b      = (const float*)d_in[8];
    const float* bn_gamma = (const float*)d_in[9];
    const float* bn_beta  = (const float*)d_in[10];
    const float* bn_mean  = (const float*)d_in[11];
    const float* bn_var   = (const float*)d_in[12];
    float* out = (float*)d_out;

    const int smem_chain = 3 * CI * PAD * (int)sizeof(float);  // 202752
    cudaFuncSetAttribute(chain_kernel,
                         cudaFuncAttributeMaxDynamicSharedMemorySize, smem_chain);
    cudaFuncSetAttribute(apply_kernel,
                         cudaFuncAttributeMaxDynamicSharedMemorySize, AP_SMEM);

    gram_kernel<<<dim3(KSPLIT, NB), 256>>>(x);
    chain_kernel<<<NB, 256, smem_chain>>>(theta_w, theta_b, phi_w, phi_b,
                                          g_w, g_b, W_w, W_b,
                                          bn_gamma, bn_beta, bn_mean, bn_var);
    apply_kernel<<<dim3(NPIX / 512, NB), 256, AP_SMEM>>>(x, out);
}